// round 12
// baseline (speedup 1.0000x reference)
#include <cuda_runtime.h>
#include <cuda_bf16.h>
#include <cuda_fp16.h>
#include <cstdint>

#define N_NODES 100000
#define N_EDGES 800000
#define F 128
#define HID 128
#define PITCH 136            // elems per row in shared tiles (conflict-free LDSM)
#define TSZ (128 * PITCH)
#define TILES (N_EDGES / 128)
#define NT_TILES ((N_NODES + 127) / 128)
#define GRID 148

// Precomputed per-node tables: A = h @ W1[0:128,:] + b1,  B = h @ W1[128:256,:]
__device__ float d_AB[2u * N_NODES * F];

// ---------------------------------------------------------------------------
__device__ __forceinline__ void mma_f16(float* c, const uint32_t* a, const uint32_t* b) {
    asm volatile(
        "mma.sync.aligned.m16n8k16.row.col.f32.f16.f16.f32 "
        "{%0,%1,%2,%3}, {%4,%5,%6,%7}, {%8,%9}, {%0,%1,%2,%3};\n"
        : "+f"(c[0]), "+f"(c[1]), "+f"(c[2]), "+f"(c[3])
        : "r"(a[0]), "r"(a[1]), "r"(a[2]), "r"(a[3]), "r"(b[0]), "r"(b[1]));
}

__device__ __forceinline__ void ldsm4(uint32_t* r, uint32_t addr) {
    asm volatile("ldmatrix.sync.aligned.m8n8.x4.shared.b16 {%0,%1,%2,%3}, [%4];"
                 : "=r"(r[0]), "=r"(r[1]), "=r"(r[2]), "=r"(r[3]) : "r"(addr));
}

__device__ __forceinline__ void split_f16(float x, __half& hi, __half& lo) {
    hi = __float2half(x);
    lo = __float2half(x - __half2float(hi));
}

__device__ __forceinline__ uint32_t smem_u32(const void* p) {
    uint32_t a;
    asm("{ .reg .u64 t; cvta.to.shared.u64 t, %1; cvt.u32.u64 %0, t; }" : "=r"(a) : "l"(p));
    return a;
}

// Per-lane LDSM byte offsets within a [row][PITCH] 16-bit tile.
__device__ __forceinline__ uint32_t ldsmA_off(int lane) {
    return (uint32_t)(((lane & 15) * PITCH + ((lane >> 4) * 8)) * 2);
}
__device__ __forceinline__ uint32_t ldsmB_off(int lane) {
    return (uint32_t)((((lane & 7) + ((lane & 16) >> 1)) * PITCH + ((lane & 8) ? 8 : 0)) * 2);
}

// ---------------------------------------------------------------------------
// Kernel 1: node GEMM — persistent, warp-specialized, fp16 2-pass (unchanged R11).
// ---------------------------------------------------------------------------
__global__ void __launch_bounds__(384, 1)
node_kernel(const float* __restrict__ h,
            const float* __restrict__ W1,
            const float* __restrict__ b1) {
    extern __shared__ __half smh[];
    __half* w_h  = smh;
    __half* w_l  = smh + TSZ;
    __half* xbuf = smh + 2 * TSZ;

    __shared__ float s_b1[128];

    const int tid  = threadIdx.x;
    const int lane = tid & 31;
    const int part = blockIdx.y;

    const float* Wp = W1 + part * F * HID;
    for (int idx = tid; idx < 128 * 128; idx += 384) {
        int k = idx >> 7, n = idx & 127;
        float w = Wp[idx];
        __half wh, wl;
        split_f16(w, wh, wl);
        w_h[n * PITCH + k] = wh;
        w_l[n * PITCH + k] = wl;
    }
    if (tid < 128) s_b1[tid] = (part == 0) ? b1[tid] : 0.f;
    __syncthreads();

    const bool is_consumer = tid < 256;
    const int  ptid = tid - 256;

    const float4* h4 = (const float4*)h;
    auto fill = [&](int buf, int t) {
        __half* x = xbuf + buf * TSZ;
        const int r0 = t * 128;
        #pragma unroll
        for (int i = 0; i < 32; i++) {
            int lin = ptid + 128 * i;
            int e = lin >> 5, v = lin & 31;
            int r = r0 + e;
            float4 a = make_float4(0.f, 0.f, 0.f, 0.f);
            if (r < N_NODES) a = h4[(size_t)r * 32 + v];
            __half2 p01 = __floats2half2_rn(a.x, a.y);
            __half2 p23 = __floats2half2_rn(a.z, a.w);
            int base = e * PITCH + v * 4;
            *(uint2*)&x[base] = make_uint2(*(uint32_t*)&p01, *(uint32_t*)&p23);
        }
    };

    if (!is_consumer) fill(0, blockIdx.x);
    __syncthreads();

    const int warp = tid >> 5;
    const int g    = lane >> 2;
    const int tig  = lane & 3;
    const int wm   = warp & 3;
    const int wn   = warp >> 2;

    const uint32_t offA = ldsmA_off(lane) + (uint32_t)(wm * 32 * PITCH * 2);
    const uint32_t offB = ldsmB_off(lane) + (uint32_t)(wn * 64 * PITCH * 2);
    const uint32_t wh_a = smem_u32(w_h) + offB;
    const uint32_t wl_a = smem_u32(w_l) + offB;

    float* table = d_AB + (size_t)part * N_NODES * F;

    int s = 0;
    for (int t = blockIdx.x; t < NT_TILES; t += GRID, s++) {
        const int buf = s & 1;
        if (is_consumer) {
            const uint32_t x_a = smem_u32(xbuf + buf * TSZ) + offA;

            float acc[2][8][4];
            #pragma unroll
            for (int mt = 0; mt < 2; mt++)
                #pragma unroll
                for (int nt = 0; nt < 8; nt++)
                    #pragma unroll
                    for (int q = 0; q < 4; q++) acc[mt][nt][q] = 0.f;

            #pragma unroll
            for (int ks = 0; ks < 8; ks++) {
                const uint32_t kb = ks * 32;

                uint32_t a[2][4];
                #pragma unroll
                for (int mt = 0; mt < 2; mt++)
                    ldsm4(a[mt], x_a + mt * (16 * PITCH * 2) + kb);

                uint32_t b_h[8][2], b_l[8][2];
                #pragma unroll
                for (int np = 0; np < 4; np++) {
                    ldsm4(&b_h[2 * np][0], wh_a + np * (16 * PITCH * 2) + kb);
                    ldsm4(&b_l[2 * np][0], wl_a + np * (16 * PITCH * 2) + kb);
                }

                #pragma unroll
                for (int mt = 0; mt < 2; mt++)
                    #pragma unroll
                    for (int nt = 0; nt < 8; nt++) {
                        mma_f16(acc[mt][nt], a[mt], b_h[nt]);
                        mma_f16(acc[mt][nt], a[mt], b_l[nt]);
                    }
            }

            const int r_base = t * 128 + wm * 32 + g;
            #pragma unroll
            for (int mt = 0; mt < 2; mt++) {
                #pragma unroll
                for (int r = 0; r < 2; r++) {
                    int row = r_base + mt * 16 + r * 8;
                    if (row < N_NODES) {
                        float* rp = table + (size_t)row * 128 + wn * 64;
                        #pragma unroll
                        for (int nt = 0; nt < 8; nt++) {
                            int c = nt * 8 + 2 * tig;
                            float2 v;
                            v.x = acc[mt][nt][2 * r]     + s_b1[wn * 64 + c];
                            v.y = acc[mt][nt][2 * r + 1] + s_b1[wn * 64 + c + 1];
                            *(float2*)(rp + c) = v;
                        }
                    }
                }
            }
        } else {
            int tn = t + GRID;
            if (tn < NT_TILES) fill(buf ^ 1, tn);
        }
        __syncthreads();
    }
}

// ---------------------------------------------------------------------------
// Kernel 2: edge kernel — single-pass plain fp16 (x fp16, W2 fp16).
// Per k-step per warp: 6 LDSM, 16 HMMA.
// ---------------------------------------------------------------------------
__global__ void __launch_bounds__(384, 1)
edge_kernel(const int* __restrict__ src,
            const int* __restrict__ dst,
            const float* __restrict__ W2,
            const float* __restrict__ b2,
            const float* __restrict__ W3,
            const float* __restrict__ b3,
            float* __restrict__ out) {
    extern __shared__ __half smh[];
    __half* w_h  = smh;                  // [n][k] transposed fp16
    __half* xbuf = smh + TSZ;            // 2 buffers, plain fp16

    __shared__ float s_b2[128];
    __shared__ float s_w3[256];
    __shared__ float s_b3[2];
    __shared__ float s_part[2][128][2];

    const int tid  = threadIdx.x;
    const int lane = tid & 31;

    for (int idx = tid; idx < 128 * 128; idx += 384) {
        int k = idx >> 7, n = idx & 127;
        w_h[n * PITCH + k] = __float2half(W2[idx]);
    }
    if (tid < 128) s_b2[tid] = b2[tid];
    if (tid < 256) s_w3[tid] = W3[tid];
    if (tid < 2)   s_b3[tid] = b3[tid];
    __syncthreads();

    const float4* A4 = (const float4*)d_AB;
    const float4* B4 = (const float4*)(d_AB + (size_t)N_NODES * F);
    const bool is_consumer = tid < 256;
    const int  ptid = tid - 256;

    auto fill = [&](int buf, int t) {
        __half* x = xbuf + buf * TSZ;
        const int e0 = t * 128;
        #pragma unroll
        for (int i = 0; i < 32; i++) {
            int lin = ptid + 128 * i;
            int e = lin >> 5, v = lin & 31;
            int si = src[e0 + e], di = dst[e0 + e];
            float4 a = A4[(size_t)si * 32 + v];
            float4 b = B4[(size_t)di * 32 + v];
            __half2 p01 = __floats2half2_rn(fmaxf(a.x + b.x, 0.f), fmaxf(a.y + b.y, 0.f));
            __half2 p23 = __floats2half2_rn(fmaxf(a.z + b.z, 0.f), fmaxf(a.w + b.w, 0.f));
            int base = e * PITCH + v * 4;
            *(uint2*)&x[base] = make_uint2(*(uint32_t*)&p01, *(uint32_t*)&p23);
        }
    };

    if (!is_consumer) fill(0, blockIdx.x);
    __syncthreads();

    const int warp = tid >> 5;
    const int g    = lane >> 2;
    const int tig  = lane & 3;
    const int wm   = warp & 3;
    const int wn   = warp >> 2;

    const uint32_t offA = ldsmA_off(lane) + (uint32_t)(wm * 32 * PITCH * 2);
    const uint32_t offB = ldsmB_off(lane) + (uint32_t)(wn * 64 * PITCH * 2);
    const uint32_t wh_a = smem_u32(w_h) + offB;

    int s = 0;
    for (int t = blockIdx.x; t < TILES; t += GRID, s++) {
        const int buf = s & 1;
        if (is_consumer) {
            const uint32_t x_a = smem_u32(xbuf + buf * TSZ) + offA;

            float acc[2][8][4];
            #pragma unroll
            for (int mt = 0; mt < 2; mt++)
                #pragma unroll
                for (int nt = 0; nt < 8; nt++)
                    #pragma unroll
                    for (int q = 0; q < 4; q++) acc[mt][nt][q] = 0.f;

            #pragma unroll
            for (int ks = 0; ks < 8; ks++) {
                const uint32_t kb = ks * 32;

                uint32_t a[2][4];
                #pragma unroll
                for (int mt = 0; mt < 2; mt++)
                    ldsm4(a[mt], x_a + mt * (16 * PITCH * 2) + kb);

                uint32_t b_h[8][2];
                #pragma unroll
                for (int np = 0; np < 4; np++)
                    ldsm4(&b_h[2 * np][0], wh_a + np * (16 * PITCH * 2) + kb);

                #pragma unroll
                for (int mt = 0; mt < 2; mt++)
                    #pragma unroll
                    for (int nt = 0; nt < 8; nt++)
                        mma_f16(acc[mt][nt], a[mt], b_h[nt]);
            }

            float p[2][2][2];
            #pragma unroll
            for (int mt = 0; mt < 2; mt++)
                #pragma unroll
                for (int r = 0; r < 2; r++) { p[mt][r][0] = 0.f; p[mt][r][1] = 0.f; }

            #pragma unroll
            for (int nt = 0; nt < 8; nt++) {
                int c0 = wn * 64 + nt * 8 + 2 * tig;
                float bb0 = s_b2[c0], bb1 = s_b2[c0 + 1];
                float w300 = s_w3[c0 * 2],       w310 = s_w3[c0 * 2 + 1];
                float w301 = s_w3[(c0 + 1) * 2], w311 = s_w3[(c0 + 1) * 2 + 1];
                #pragma unroll
                for (int mt = 0; mt < 2; mt++) {
                    float x00 = fmaxf(acc[mt][nt][0] + bb0, 0.f);
                    float x01 = fmaxf(acc[mt][nt][1] + bb1, 0.f);
                    float x10 = fmaxf(acc[mt][nt][2] + bb0, 0.f);
                    float x11 = fmaxf(acc[mt][nt][3] + bb1, 0.f);
                    p[mt][0][0] = fmaf(x00, w300, fmaf(x01, w301, p[mt][0][0]));
                    p[mt][0][1] = fmaf(x00, w310, fmaf(x01, w311, p[mt][0][1]));
                    p[mt][1][0] = fmaf(x10, w300, fmaf(x11, w301, p[mt][1][0]));
                    p[mt][1][1] = fmaf(x10, w310, fmaf(x11, w311, p[mt][1][1]));
                }
            }

            #pragma unroll
            for (int mt = 0; mt < 2; mt++)
                #pragma unroll
                for (int r = 0; r < 2; r++)
                    #pragma unroll
                    for (int o = 0; o < 2; o++) {
                        float v = p[mt][r][o];
                        v += __shfl_xor_sync(0xffffffffu, v, 1);
                        v += __shfl_xor_sync(0xffffffffu, v, 2);
                        p[mt][r][o] = v;
                    }

            if (tig == 0) {
                #pragma unroll
                for (int mt = 0; mt < 2; mt++) {
                    int r0 = wm * 32 + mt * 16 + g;
                    s_part[wn][r0][0]     = p[mt][0][0];
                    s_part[wn][r0][1]     = p[mt][0][1];
                    s_part[wn][r0 + 8][0] = p[mt][1][0];
                    s_part[wn][r0 + 8][1] = p[mt][1][1];
                }
            }
            asm volatile("bar.sync 1, 256;" ::: "memory");
            out[(size_t)t * 256 + tid] =
                s_part[0][tid >> 1][tid & 1] + s_part[1][tid >> 1][tid & 1] + s_b3[tid & 1];
        } else {
            int tn = t + GRID;
            if (tn < TILES) fill(buf ^ 1, tn);
        }
        __syncthreads();
    }
}

// ---------------------------------------------------------------------------
extern "C" void kernel_launch(void* const* d_in, const int* in_sizes, int n_in,
                              void* d_out, int out_size) {
    const float* h   = (const float*)d_in[0];
    const int*   src = (const int*)d_in[1];
    const int*   dst = (const int*)d_in[2];
    const float* W1  = (const float*)d_in[3];
    const float* b1  = (const float*)d_in[4];
    const float* W2  = (const float*)d_in[5];
    const float* b2  = (const float*)d_in[6];
    const float* W3  = (const float*)d_in[7];
    const float* b3  = (const float*)d_in[8];
    float* out = (float*)d_out;

    const int node_smem = 4 * TSZ * (int)sizeof(__half);   // 139264
    const int edge_smem = 3 * TSZ * (int)sizeof(__half);   // 104448
    cudaFuncSetAttribute(node_kernel, cudaFuncAttributeMaxDynamicSharedMemorySize, node_smem);
    cudaFuncSetAttribute(edge_kernel, cudaFuncAttributeMaxDynamicSharedMemorySize, edge_smem);

    node_kernel<<<dim3(GRID, 2), 384, node_smem>>>(h, W1, b1);
    edge_kernel<<<GRID, 384, edge_smem>>>(src, dst, W2, b2, W3, b3, out);
}

// round 13
// speedup vs baseline: 1.5013x; 1.5013x over previous
#include <cuda_runtime.h>
#include <cuda_bf16.h>
#include <cuda_fp16.h>
#include <cstdint>

#define N_NODES 100000
#define N_EDGES 800000
#define F 128
#define HID 128
#define PITCH 136            // elems per row in shared tiles (conflict-free LDSM)
#define TSZ (128 * PITCH)
#define TILES (N_EDGES / 128)
#define NT_TILES ((N_NODES + 127) / 128)
#define GRID 148

// Precomputed per-node tables in fp16: A = h@W1[0:128,:]+b1, B = h@W1[128:256,:]
// 2 * 100000 * 128 * 2 bytes = 51.2 MB — fully L2-resident (126 MB L2).
__device__ __half d_AB[2u * N_NODES * F];

// ---------------------------------------------------------------------------
__device__ __forceinline__ void mma_f16(float* c, const uint32_t* a, const uint32_t* b) {
    asm volatile(
        "mma.sync.aligned.m16n8k16.row.col.f32.f16.f16.f32 "
        "{%0,%1,%2,%3}, {%4,%5,%6,%7}, {%8,%9}, {%0,%1,%2,%3};\n"
        : "+f"(c[0]), "+f"(c[1]), "+f"(c[2]), "+f"(c[3])
        : "r"(a[0]), "r"(a[1]), "r"(a[2]), "r"(a[3]), "r"(b[0]), "r"(b[1]));
}

__device__ __forceinline__ void ldsm4(uint32_t* r, uint32_t addr) {
    asm volatile("ldmatrix.sync.aligned.m8n8.x4.shared.b16 {%0,%1,%2,%3}, [%4];"
                 : "=r"(r[0]), "=r"(r[1]), "=r"(r[2]), "=r"(r[3]) : "r"(addr));
}

__device__ __forceinline__ void split_f16(float x, __half& hi, __half& lo) {
    hi = __float2half(x);
    lo = __float2half(x - __half2float(hi));
}

__device__ __forceinline__ uint32_t smem_u32(const void* p) {
    uint32_t a;
    asm("{ .reg .u64 t; cvta.to.shared.u64 t, %1; cvt.u32.u64 %0, t; }" : "=r"(a) : "l"(p));
    return a;
}

// Per-lane LDSM byte offsets within a [row][PITCH] 16-bit tile.
__device__ __forceinline__ uint32_t ldsmA_off(int lane) {
    return (uint32_t)(((lane & 15) * PITCH + ((lane >> 4) * 8)) * 2);
}
__device__ __forceinline__ uint32_t ldsmB_off(int lane) {
    return (uint32_t)((((lane & 7) + ((lane & 16) >> 1)) * PITCH + ((lane & 8) ? 8 : 0)) * 2);
}

// ---------------------------------------------------------------------------
// Kernel 1: node GEMM — persistent, warp-specialized, fp16 2-pass.
// Epilogue now stores half2 directly into the fp16 tables.
// ---------------------------------------------------------------------------
__global__ void __launch_bounds__(384, 1)
node_kernel(const float* __restrict__ h,
            const float* __restrict__ W1,
            const float* __restrict__ b1) {
    extern __shared__ __half smh[];
    __half* w_h  = smh;
    __half* w_l  = smh + TSZ;
    __half* xbuf = smh + 2 * TSZ;

    __shared__ float s_b1[128];

    const int tid  = threadIdx.x;
    const int lane = tid & 31;
    const int part = blockIdx.y;

    const float* Wp = W1 + part * F * HID;
    for (int idx = tid; idx < 128 * 128; idx += 384) {
        int k = idx >> 7, n = idx & 127;
        float w = Wp[idx];
        __half wh, wl;
        split_f16(w, wh, wl);
        w_h[n * PITCH + k] = wh;
        w_l[n * PITCH + k] = wl;
    }
    if (tid < 128) s_b1[tid] = (part == 0) ? b1[tid] : 0.f;
    __syncthreads();

    const bool is_consumer = tid < 256;
    const int  ptid = tid - 256;

    const float4* h4 = (const float4*)h;
    auto fill = [&](int buf, int t) {
        __half* x = xbuf + buf * TSZ;
        const int r0 = t * 128;
        #pragma unroll
        for (int i = 0; i < 32; i++) {
            int lin = ptid + 128 * i;
            int e = lin >> 5, v = lin & 31;
            int r = r0 + e;
            float4 a = make_float4(0.f, 0.f, 0.f, 0.f);
            if (r < N_NODES) a = h4[(size_t)r * 32 + v];
            __half2 p01 = __floats2half2_rn(a.x, a.y);
            __half2 p23 = __floats2half2_rn(a.z, a.w);
            int base = e * PITCH + v * 4;
            *(uint2*)&x[base] = make_uint2(*(uint32_t*)&p01, *(uint32_t*)&p23);
        }
    };

    if (!is_consumer) fill(0, blockIdx.x);
    __syncthreads();

    const int warp = tid >> 5;
    const int g    = lane >> 2;
    const int tig  = lane & 3;
    const int wm   = warp & 3;
    const int wn   = warp >> 2;

    const uint32_t offA = ldsmA_off(lane) + (uint32_t)(wm * 32 * PITCH * 2);
    const uint32_t offB = ldsmB_off(lane) + (uint32_t)(wn * 64 * PITCH * 2);
    const uint32_t wh_a = smem_u32(w_h) + offB;
    const uint32_t wl_a = smem_u32(w_l) + offB;

    __half* table = d_AB + (size_t)part * N_NODES * F;

    int s = 0;
    for (int t = blockIdx.x; t < NT_TILES; t += GRID, s++) {
        const int buf = s & 1;
        if (is_consumer) {
            const uint32_t x_a = smem_u32(xbuf + buf * TSZ) + offA;

            float acc[2][8][4];
            #pragma unroll
            for (int mt = 0; mt < 2; mt++)
                #pragma unroll
                for (int nt = 0; nt < 8; nt++)
                    #pragma unroll
                    for (int q = 0; q < 4; q++) acc[mt][nt][q] = 0.f;

            #pragma unroll
            for (int ks = 0; ks < 8; ks++) {
                const uint32_t kb = ks * 32;

                uint32_t a[2][4];
                #pragma unroll
                for (int mt = 0; mt < 2; mt++)
                    ldsm4(a[mt], x_a + mt * (16 * PITCH * 2) + kb);

                uint32_t b_h[8][2], b_l[8][2];
                #pragma unroll
                for (int np = 0; np < 4; np++) {
                    ldsm4(&b_h[2 * np][0], wh_a + np * (16 * PITCH * 2) + kb);
                    ldsm4(&b_l[2 * np][0], wl_a + np * (16 * PITCH * 2) + kb);
                }

                #pragma unroll
                for (int mt = 0; mt < 2; mt++)
                    #pragma unroll
                    for (int nt = 0; nt < 8; nt++) {
                        mma_f16(acc[mt][nt], a[mt], b_h[nt]);
                        mma_f16(acc[mt][nt], a[mt], b_l[nt]);
                    }
            }

            const int r_base = t * 128 + wm * 32 + g;
            #pragma unroll
            for (int mt = 0; mt < 2; mt++) {
                #pragma unroll
                for (int r = 0; r < 2; r++) {
                    int row = r_base + mt * 16 + r * 8;
                    if (row < N_NODES) {
                        __half* rp = table + (size_t)row * 128 + wn * 64;
                        #pragma unroll
                        for (int nt = 0; nt < 8; nt++) {
                            int c = nt * 8 + 2 * tig;
                            __half2 v = __floats2half2_rn(
                                acc[mt][nt][2 * r]     + s_b1[wn * 64 + c],
                                acc[mt][nt][2 * r + 1] + s_b1[wn * 64 + c + 1]);
                            *(__half2*)(rp + c) = v;
                        }
                    }
                }
            }
        } else {
            int tn = t + GRID;
            if (tn < NT_TILES) fill(buf ^ 1, tn);
        }
        __syncthreads();
    }
}

// ---------------------------------------------------------------------------
// Kernel 2: edge kernel — 512 threads: 8 consumer warps (single-pass fp16,
// 32x64 tiles) + 8 producer warps (fp16-table gather, HADD2/HMAX2).
// ---------------------------------------------------------------------------
__global__ void __launch_bounds__(512, 1)
edge_kernel(const int* __restrict__ src,
            const int* __restrict__ dst,
            const float* __restrict__ W2,
            const float* __restrict__ b2,
            const float* __restrict__ W3,
            const float* __restrict__ b3,
            float* __restrict__ out) {
    extern __shared__ __half smh[];
    __half* w_h  = smh;                  // [n][k] transposed fp16
    __half* xbuf = smh + TSZ;            // 2 buffers, fp16

    __shared__ float s_b2[128];
    __shared__ float s_w3[256];
    __shared__ float s_b3[2];
    __shared__ float s_part[2][128][2];

    const int tid  = threadIdx.x;
    const int lane = tid & 31;

    for (int idx = tid; idx < 128 * 128; idx += 512) {
        int k = idx >> 7, n = idx & 127;
        w_h[n * PITCH + k] = __float2half(W2[idx]);
    }
    if (tid < 128) s_b2[tid] = b2[tid];
    if (tid < 256) s_w3[tid] = W3[tid];
    if (tid < 2)   s_b3[tid] = b3[tid];
    __syncthreads();

    const uint2* A2 = (const uint2*)d_AB;
    const uint2* B2 = (const uint2*)(d_AB + (size_t)N_NODES * F);
    const bool is_consumer = tid < 256;
    const int  ptid = tid - 256;          // producers: 256 threads (8 warps)

    auto fill = [&](int buf, int t) {
        __half* x = xbuf + buf * TSZ;
        const int e0 = t * 128;
        const __half2 z2 = __float2half2_rn(0.f);
        #pragma unroll
        for (int i = 0; i < 16; i++) {
            int lin = ptid + 256 * i;
            int e = lin >> 5, v = lin & 31;
            int si = src[e0 + e], di = dst[e0 + e];
            uint2 a = A2[(size_t)si * 32 + v];
            uint2 b = B2[(size_t)di * 32 + v];
            __half2 s01 = __hmax2(__hadd2(*(__half2*)&a.x, *(__half2*)&b.x), z2);
            __half2 s23 = __hmax2(__hadd2(*(__half2*)&a.y, *(__half2*)&b.y), z2);
            int base = e * PITCH + v * 4;
            *(uint2*)&x[base] = make_uint2(*(uint32_t*)&s01, *(uint32_t*)&s23);
        }
    };

    if (!is_consumer) fill(0, blockIdx.x);
    __syncthreads();

    const int warp = tid >> 5;
    const int g    = lane >> 2;
    const int tig  = lane & 3;
    const int wm   = warp & 3;
    const int wn   = warp >> 2;           // 0/1 for consumer warps

    const uint32_t offA = ldsmA_off(lane) + (uint32_t)(wm * 32 * PITCH * 2);
    const uint32_t offB = ldsmB_off(lane) + (uint32_t)(wn * 64 * PITCH * 2);
    const uint32_t wh_a = smem_u32(w_h) + offB;

    int s = 0;
    for (int t = blockIdx.x; t < TILES; t += GRID, s++) {
        const int buf = s & 1;
        if (is_consumer) {
            const uint32_t x_a = smem_u32(xbuf + buf * TSZ) + offA;

            float acc[2][8][4];
            #pragma unroll
            for (int mt = 0; mt < 2; mt++)
                #pragma unroll
                for (int nt = 0; nt < 8; nt++)
                    #pragma unroll
                    for (int q = 0; q < 4; q++) acc[mt][nt][q] = 0.f;

            #pragma unroll
            for (int ks = 0; ks < 8; ks++) {
                const uint32_t kb = ks * 32;

                uint32_t a[2][4];
                #pragma unroll
                for (int mt = 0; mt < 2; mt++)
                    ldsm4(a[mt], x_a + mt * (16 * PITCH * 2) + kb);

                uint32_t b_h[8][2];
                #pragma unroll
                for (int np = 0; np < 4; np++)
                    ldsm4(&b_h[2 * np][0], wh_a + np * (16 * PITCH * 2) + kb);

                #pragma unroll
                for (int mt = 0; mt < 2; mt++)
                    #pragma unroll
                    for (int nt = 0; nt < 8; nt++)
                        mma_f16(acc[mt][nt], a[mt], b_h[nt]);
            }

            float p[2][2][2];
            #pragma unroll
            for (int mt = 0; mt < 2; mt++)
                #pragma unroll
                for (int r = 0; r < 2; r++) { p[mt][r][0] = 0.f; p[mt][r][1] = 0.f; }

            #pragma unroll
            for (int nt = 0; nt < 8; nt++) {
                int c0 = wn * 64 + nt * 8 + 2 * tig;
                float bb0 = s_b2[c0], bb1 = s_b2[c0 + 1];
                float w300 = s_w3[c0 * 2],       w310 = s_w3[c0 * 2 + 1];
                float w301 = s_w3[(c0 + 1) * 2], w311 = s_w3[(c0 + 1) * 2 + 1];
                #pragma unroll
                for (int mt = 0; mt < 2; mt++) {
                    float x00 = fmaxf(acc[mt][nt][0] + bb0, 0.f);
                    float x01 = fmaxf(acc[mt][nt][1] + bb1, 0.f);
                    float x10 = fmaxf(acc[mt][nt][2] + bb0, 0.f);
                    float x11 = fmaxf(acc[mt][nt][3] + bb1, 0.f);
                    p[mt][0][0] = fmaf(x00, w300, fmaf(x01, w301, p[mt][0][0]));
                    p[mt][0][1] = fmaf(x00, w310, fmaf(x01, w311, p[mt][0][1]));
                    p[mt][1][0] = fmaf(x10, w300, fmaf(x11, w301, p[mt][1][0]));
                    p[mt][1][1] = fmaf(x10, w310, fmaf(x11, w311, p[mt][1][1]));
                }
            }

            #pragma unroll
            for (int mt = 0; mt < 2; mt++)
                #pragma unroll
                for (int r = 0; r < 2; r++)
                    #pragma unroll
                    for (int o = 0; o < 2; o++) {
                        float v = p[mt][r][o];
                        v += __shfl_xor_sync(0xffffffffu, v, 1);
                        v += __shfl_xor_sync(0xffffffffu, v, 2);
                        p[mt][r][o] = v;
                    }

            if (tig == 0) {
                #pragma unroll
                for (int mt = 0; mt < 2; mt++) {
                    int r0 = wm * 32 + mt * 16 + g;
                    s_part[wn][r0][0]     = p[mt][0][0];
                    s_part[wn][r0][1]     = p[mt][0][1];
                    s_part[wn][r0 + 8][0] = p[mt][1][0];
                    s_part[wn][r0 + 8][1] = p[mt][1][1];
                }
            }
            asm volatile("bar.sync 1, 256;" ::: "memory");
            out[(size_t)t * 256 + tid] =
                s_part[0][tid >> 1][tid & 1] + s_part[1][tid >> 1][tid & 1] + s_b3[tid & 1];
        } else {
            int tn = t + GRID;
            if (tn < TILES) fill(buf ^ 1, tn);
        }
        __syncthreads();
    }
}

// ---------------------------------------------------------------------------
extern "C" void kernel_launch(void* const* d_in, const int* in_sizes, int n_in,
                              void* d_out, int out_size) {
    const float* h   = (const float*)d_in[0];
    const int*   src = (const int*)d_in[1];
    const int*   dst = (const int*)d_in[2];
    const float* W1  = (const float*)d_in[3];
    const float* b1  = (const float*)d_in[4];
    const float* W2  = (const float*)d_in[5];
    const float* b2  = (const float*)d_in[6];
    const float* W3  = (const float*)d_in[7];
    const float* b3  = (const float*)d_in[8];
    float* out = (float*)d_out;

    const int node_smem = 4 * TSZ * (int)sizeof(__half);   // 139264
    const int edge_smem = 3 * TSZ * (int)sizeof(__half);   // 104448
    cudaFuncSetAttribute(node_kernel, cudaFuncAttributeMaxDynamicSharedMemorySize, node_smem);
    cudaFuncSetAttribute(edge_kernel, cudaFuncAttributeMaxDynamicSharedMemorySize, edge_smem);

    node_kernel<<<dim3(GRID, 2), 384, node_smem>>>(h, W1, b1);
    edge_kernel<<<GRID, 512, edge_smem>>>(src, dst, W2, b2, W3, b3, out);
}

// round 14
// speedup vs baseline: 1.6833x; 1.1213x over previous
#include <cuda_runtime.h>
#include <cuda_bf16.h>
#include <cuda_fp16.h>
#include <cstdint>

#define N_NODES 100000
#define N_EDGES 800000
#define F 128
#define HID 128
#define PITCH 136            // elems per row in shared tiles (conflict-free LDSM)
#define TSZ (128 * PITCH)
#define TILES (N_EDGES / 128)
#define NT_TILES ((N_NODES + 127) / 128)
#define GRID 148

// Precomputed per-node tables in fp16: A = h@W1[0:128,:]+b1, B = h@W1[128:256,:]
// 51.2 MB — fully L2-resident.
__device__ __half d_AB[2u * N_NODES * F];

// ---------------------------------------------------------------------------
__device__ __forceinline__ void mma_f16(float* c, const uint32_t* a, const uint32_t* b) {
    asm volatile(
        "mma.sync.aligned.m16n8k16.row.col.f32.f16.f16.f32 "
        "{%0,%1,%2,%3}, {%4,%5,%6,%7}, {%8,%9}, {%0,%1,%2,%3};\n"
        : "+f"(c[0]), "+f"(c[1]), "+f"(c[2]), "+f"(c[3])
        : "r"(a[0]), "r"(a[1]), "r"(a[2]), "r"(a[3]), "r"(b[0]), "r"(b[1]));
}

__device__ __forceinline__ void ldsm4(uint32_t* r, uint32_t addr) {
    asm volatile("ldmatrix.sync.aligned.m8n8.x4.shared.b16 {%0,%1,%2,%3}, [%4];"
                 : "=r"(r[0]), "=r"(r[1]), "=r"(r[2]), "=r"(r[3]) : "r"(addr));
}

__device__ __forceinline__ uint32_t smem_u32(const void* p) {
    uint32_t a;
    asm("{ .reg .u64 t; cvta.to.shared.u64 t, %1; cvt.u32.u64 %0, t; }" : "=r"(a) : "l"(p));
    return a;
}

// Per-lane LDSM byte offsets within a [row][PITCH] 16-bit tile.
__device__ __forceinline__ uint32_t ldsmA_off(int lane) {
    return (uint32_t)(((lane & 15) * PITCH + ((lane >> 4) * 8)) * 2);
}
__device__ __forceinline__ uint32_t ldsmB_off(int lane) {
    return (uint32_t)((((lane & 7) + ((lane & 16) >> 1)) * PITCH + ((lane & 8) ? 8 : 0)) * 2);
}

// ---------------------------------------------------------------------------
// Kernel 1: node GEMM — 512 threads: 8 consumer warps (single-pass fp16) +
// 8 producer warps (h fp32 -> fp16). grid (148, 2): y = part.
// ---------------------------------------------------------------------------
__global__ void __launch_bounds__(512, 1)
node_kernel(const float* __restrict__ h,
            const float* __restrict__ W1,
            const float* __restrict__ b1) {
    extern __shared__ __half smh[];
    __half* w_h  = smh;                  // [n][k] transposed fp16
    __half* xbuf = smh + TSZ;            // 2 buffers, fp16

    __shared__ float s_b1[128];

    const int tid  = threadIdx.x;
    const int lane = tid & 31;
    const int part = blockIdx.y;

    const float* Wp = W1 + part * F * HID;
    for (int idx = tid; idx < 128 * 128; idx += 512) {
        int k = idx >> 7, n = idx & 127;
        w_h[n * PITCH + k] = __float2half(Wp[idx]);
    }
    if (tid < 128) s_b1[tid] = (part == 0) ? b1[tid] : 0.f;
    __syncthreads();

    const bool is_consumer = tid < 256;
    const int  ptid = tid - 256;          // producers: 256 threads (8 warps)

    const float4* h4 = (const float4*)h;
    auto fill = [&](int buf, int t) {
        __half* x = xbuf + buf * TSZ;
        const int r0 = t * 128;
        #pragma unroll
        for (int i = 0; i < 16; i++) {
            int lin = ptid + 256 * i;
            int e = lin >> 5, v = lin & 31;
            int r = r0 + e;
            float4 a = make_float4(0.f, 0.f, 0.f, 0.f);
            if (r < N_NODES) a = h4[(size_t)r * 32 + v];
            __half2 p01 = __floats2half2_rn(a.x, a.y);
            __half2 p23 = __floats2half2_rn(a.z, a.w);
            int base = e * PITCH + v * 4;
            *(uint2*)&x[base] = make_uint2(*(uint32_t*)&p01, *(uint32_t*)&p23);
        }
    };

    if (!is_consumer) fill(0, blockIdx.x);
    __syncthreads();

    const int warp = tid >> 5;
    const int g    = lane >> 2;
    const int tig  = lane & 3;
    const int wm   = warp & 3;
    const int wn   = warp >> 2;           // 0/1 for consumer warps

    const uint32_t offA = ldsmA_off(lane) + (uint32_t)(wm * 32 * PITCH * 2);
    const uint32_t offB = ldsmB_off(lane) + (uint32_t)(wn * 64 * PITCH * 2);
    const uint32_t wh_a = smem_u32(w_h) + offB;

    __half* table = d_AB + (size_t)part * N_NODES * F;

    int s = 0;
    for (int t = blockIdx.x; t < NT_TILES; t += GRID, s++) {
        const int buf = s & 1;
        if (is_consumer) {
            const uint32_t x_a = smem_u32(xbuf + buf * TSZ) + offA;

            float acc[2][8][4];
            #pragma unroll
            for (int mt = 0; mt < 2; mt++)
                #pragma unroll
                for (int nt = 0; nt < 8; nt++)
                    #pragma unroll
                    for (int q = 0; q < 4; q++) acc[mt][nt][q] = 0.f;

            #pragma unroll
            for (int ks = 0; ks < 8; ks++) {
                const uint32_t kb = ks * 32;

                uint32_t a[2][4];
                #pragma unroll
                for (int mt = 0; mt < 2; mt++)
                    ldsm4(a[mt], x_a + mt * (16 * PITCH * 2) + kb);

                uint32_t b_h[8][2];
                #pragma unroll
                for (int np = 0; np < 4; np++)
                    ldsm4(&b_h[2 * np][0], wh_a + np * (16 * PITCH * 2) + kb);

                #pragma unroll
                for (int mt = 0; mt < 2; mt++)
                    #pragma unroll
                    for (int nt = 0; nt < 8; nt++)
                        mma_f16(acc[mt][nt], a[mt], b_h[nt]);
            }

            const int r_base = t * 128 + wm * 32 + g;
            #pragma unroll
            for (int mt = 0; mt < 2; mt++) {
                #pragma unroll
                for (int r = 0; r < 2; r++) {
                    int row = r_base + mt * 16 + r * 8;
                    if (row < N_NODES) {
                        __half* rp = table + (size_t)row * 128 + wn * 64;
                        #pragma unroll
                        for (int nt = 0; nt < 8; nt++) {
                            int c = nt * 8 + 2 * tig;
                            __half2 v = __floats2half2_rn(
                                acc[mt][nt][2 * r]     + s_b1[wn * 64 + c],
                                acc[mt][nt][2 * r + 1] + s_b1[wn * 64 + c + 1]);
                            *(__half2*)(rp + c) = v;
                        }
                    }
                }
            }
        } else {
            int tn = t + GRID;
            if (tn < NT_TILES) fill(buf ^ 1, tn);
        }
        __syncthreads();
    }
}

// ---------------------------------------------------------------------------
// Kernel 2: edge kernel — unchanged from R13 (512 thr, single-pass fp16).
// ---------------------------------------------------------------------------
__global__ void __launch_bounds__(512, 1)
edge_kernel(const int* __restrict__ src,
            const int* __restrict__ dst,
            const float* __restrict__ W2,
            const float* __restrict__ b2,
            const float* __restrict__ W3,
            const float* __restrict__ b3,
            float* __restrict__ out) {
    extern __shared__ __half smh[];
    __half* w_h  = smh;
    __half* xbuf = smh + TSZ;

    __shared__ float s_b2[128];
    __shared__ float s_w3[256];
    __shared__ float s_b3[2];
    __shared__ float s_part[2][128][2];

    const int tid  = threadIdx.x;
    const int lane = tid & 31;

    for (int idx = tid; idx < 128 * 128; idx += 512) {
        int k = idx >> 7, n = idx & 127;
        w_h[n * PITCH + k] = __float2half(W2[idx]);
    }
    if (tid < 128) s_b2[tid] = b2[tid];
    if (tid < 256) s_w3[tid] = W3[tid];
    if (tid < 2)   s_b3[tid] = b3[tid];
    __syncthreads();

    const uint2* A2 = (const uint2*)d_AB;
    const uint2* B2 = (const uint2*)(d_AB + (size_t)N_NODES * F);
    const bool is_consumer = tid < 256;
    const int  ptid = tid - 256;

    auto fill = [&](int buf, int t) {
        __half* x = xbuf + buf * TSZ;
        const int e0 = t * 128;
        const __half2 z2 = __float2half2_rn(0.f);
        #pragma unroll
        for (int i = 0; i < 16; i++) {
            int lin = ptid + 256 * i;
            int e = lin >> 5, v = lin & 31;
            int si = src[e0 + e], di = dst[e0 + e];
            uint2 a = A2[(size_t)si * 32 + v];
            uint2 b = B2[(size_t)di * 32 + v];
            __half2 s01 = __hmax2(__hadd2(*(__half2*)&a.x, *(__half2*)&b.x), z2);
            __half2 s23 = __hmax2(__hadd2(*(__half2*)&a.y, *(__half2*)&b.y), z2);
            int base = e * PITCH + v * 4;
            *(uint2*)&x[base] = make_uint2(*(uint32_t*)&s01, *(uint32_t*)&s23);
        }
    };

    if (!is_consumer) fill(0, blockIdx.x);
    __syncthreads();

    const int warp = tid >> 5;
    const int g    = lane >> 2;
    const int tig  = lane & 3;
    const int wm   = warp & 3;
    const int wn   = warp >> 2;

    const uint32_t offA = ldsmA_off(lane) + (uint32_t)(wm * 32 * PITCH * 2);
    const uint32_t offB = ldsmB_off(lane) + (uint32_t)(wn * 64 * PITCH * 2);
    const uint32_t wh_a = smem_u32(w_h) + offB;

    int s = 0;
    for (int t = blockIdx.x; t < TILES; t += GRID, s++) {
        const int buf = s & 1;
        if (is_consumer) {
            const uint32_t x_a = smem_u32(xbuf + buf * TSZ) + offA;

            float acc[2][8][4];
            #pragma unroll
            for (int mt = 0; mt < 2; mt++)
                #pragma unroll
                for (int nt = 0; nt < 8; nt++)
                    #pragma unroll
                    for (int q = 0; q < 4; q++) acc[mt][nt][q] = 0.f;

            #pragma unroll
            for (int ks = 0; ks < 8; ks++) {
                const uint32_t kb = ks * 32;

                uint32_t a[2][4];
                #pragma unroll
                for (int mt = 0; mt < 2; mt++)
                    ldsm4(a[mt], x_a + mt * (16 * PITCH * 2) + kb);

                uint32_t b_h[8][2];
                #pragma unroll
                for (int np = 0; np < 4; np++)
                    ldsm4(&b_h[2 * np][0], wh_a + np * (16 * PITCH * 2) + kb);

                #pragma unroll
                for (int mt = 0; mt < 2; mt++)
                    #pragma unroll
                    for (int nt = 0; nt < 8; nt++)
                        mma_f16(acc[mt][nt], a[mt], b_h[nt]);
            }

            float p[2][2][2];
            #pragma unroll
            for (int mt = 0; mt < 2; mt++)
                #pragma unroll
                for (int r = 0; r < 2; r++) { p[mt][r][0] = 0.f; p[mt][r][1] = 0.f; }

            #pragma unroll
            for (int nt = 0; nt < 8; nt++) {
                int c0 = wn * 64 + nt * 8 + 2 * tig;
                float bb0 = s_b2[c0], bb1 = s_b2[c0 + 1];
                float w300 = s_w3[c0 * 2],       w310 = s_w3[c0 * 2 + 1];
                float w301 = s_w3[(c0 + 1) * 2], w311 = s_w3[(c0 + 1) * 2 + 1];
                #pragma unroll
                for (int mt = 0; mt < 2; mt++) {
                    float x00 = fmaxf(acc[mt][nt][0] + bb0, 0.f);
                    float x01 = fmaxf(acc[mt][nt][1] + bb1, 0.f);
                    float x10 = fmaxf(acc[mt][nt][2] + bb0, 0.f);
                    float x11 = fmaxf(acc[mt][nt][3] + bb1, 0.f);
                    p[mt][0][0] = fmaf(x00, w300, fmaf(x01, w301, p[mt][0][0]));
                    p[mt][0][1] = fmaf(x00, w310, fmaf(x01, w311, p[mt][0][1]));
                    p[mt][1][0] = fmaf(x10, w300, fmaf(x11, w301, p[mt][1][0]));
                    p[mt][1][1] = fmaf(x10, w310, fmaf(x11, w311, p[mt][1][1]));
                }
            }

            #pragma unroll
            for (int mt = 0; mt < 2; mt++)
                #pragma unroll
                for (int r = 0; r < 2; r++)
                    #pragma unroll
                    for (int o = 0; o < 2; o++) {
                        float v = p[mt][r][o];
                        v += __shfl_xor_sync(0xffffffffu, v, 1);
                        v += __shfl_xor_sync(0xffffffffu, v, 2);
                        p[mt][r][o] = v;
                    }

            if (tig == 0) {
                #pragma unroll
                for (int mt = 0; mt < 2; mt++) {
                    int r0 = wm * 32 + mt * 16 + g;
                    s_part[wn][r0][0]     = p[mt][0][0];
                    s_part[wn][r0][1]     = p[mt][0][1];
                    s_part[wn][r0 + 8][0] = p[mt][1][0];
                    s_part[wn][r0 + 8][1] = p[mt][1][1];
                }
            }
            asm volatile("bar.sync 1, 256;" ::: "memory");
            out[(size_t)t * 256 + tid] =
                s_part[0][tid >> 1][tid & 1] + s_part[1][tid >> 1][tid & 1] + s_b3[tid & 1];
        } else {
            int tn = t + GRID;
            if (tn < TILES) fill(buf ^ 1, tn);
        }
        __syncthreads();
    }
}

// ---------------------------------------------------------------------------
extern "C" void kernel_launch(void* const* d_in, const int* in_sizes, int n_in,
                              void* d_out, int out_size) {
    const float* h   = (const float*)d_in[0];
    const int*   src = (const int*)d_in[1];
    const int*   dst = (const int*)d_in[2];
    const float* W1  = (const float*)d_in[3];
    const float* b1  = (const float*)d_in[4];
    const float* W2  = (const float*)d_in[5];
    const float* b2  = (const float*)d_in[6];
    const float* W3  = (const float*)d_in[7];
    const float* b3  = (const float*)d_in[8];
    float* out = (float*)d_out;

    const int smem = 3 * TSZ * (int)sizeof(__half);   // 104448
    cudaFuncSetAttribute(node_kernel, cudaFuncAttributeMaxDynamicSharedMemorySize, smem);
    cudaFuncSetAttribute(edge_kernel, cudaFuncAttributeMaxDynamicSharedMemorySize, smem);

    node_kernel<<<dim3(GRID, 2), 512, smem>>>(h, W1, b1);
    edge_kernel<<<GRID, 512, smem>>>(src, dst, W2, b2, W3, b3, out);
}

// round 15
// speedup vs baseline: 1.7544x; 1.0422x over previous
#include <cuda_runtime.h>
#include <cuda_bf16.h>
#include <cuda_fp16.h>
#include <cstdint>

#define N_NODES 100000
#define N_EDGES 800000
#define F 128
#define HID 128
#define PITCH 136            // elems per row in shared tiles (conflict-free LDSM)
#define TSZ (128 * PITCH)
#define TILES (N_EDGES / 128)
#define NT_TILES ((N_NODES + 127) / 128)
#define GRID 148

// Precomputed per-node tables in fp16: A = h@W1[0:128,:]+b1, B = h@W1[128:256,:]
// 51.2 MB — fully L2-resident.
__device__ __half d_AB[2u * N_NODES * F];

// ---------------------------------------------------------------------------
__device__ __forceinline__ void mma_f16(float* c, const uint32_t* a, const uint32_t* b) {
    asm volatile(
        "mma.sync.aligned.m16n8k16.row.col.f32.f16.f16.f32 "
        "{%0,%1,%2,%3}, {%4,%5,%6,%7}, {%8,%9}, {%0,%1,%2,%3};\n"
        : "+f"(c[0]), "+f"(c[1]), "+f"(c[2]), "+f"(c[3])
        : "r"(a[0]), "r"(a[1]), "r"(a[2]), "r"(a[3]), "r"(b[0]), "r"(b[1]));
}

__device__ __forceinline__ void ldsm4(uint32_t* r, uint32_t addr) {
    asm volatile("ldmatrix.sync.aligned.m8n8.x4.shared.b16 {%0,%1,%2,%3}, [%4];"
                 : "=r"(r[0]), "=r"(r[1]), "=r"(r[2]), "=r"(r[3]) : "r"(addr));
}

__device__ __forceinline__ uint32_t smem_u32(const void* p) {
    uint32_t a;
    asm("{ .reg .u64 t; cvta.to.shared.u64 t, %1; cvt.u32.u64 %0, t; }" : "=r"(a) : "l"(p));
    return a;
}

// Per-lane LDSM byte offsets within a [row][PITCH] 16-bit tile.
__device__ __forceinline__ uint32_t ldsmA_off(int lane) {
    return (uint32_t)(((lane & 15) * PITCH + ((lane >> 4) * 8)) * 2);
}
__device__ __forceinline__ uint32_t ldsmB_off(int lane) {
    return (uint32_t)((((lane & 7) + ((lane & 16) >> 1)) * PITCH + ((lane & 8) ? 8 : 0)) * 2);
}

// ---------------------------------------------------------------------------
// Kernel 1: node GEMM — merged: each 128-node tile computes BOTH tables
// (h read/converted once). 512 threads: 8 consumers + 8 producers. grid 148.
// ---------------------------------------------------------------------------
__global__ void __launch_bounds__(512, 1)
node_kernel(const float* __restrict__ h,
            const float* __restrict__ W1,
            const float* __restrict__ b1) {
    extern __shared__ __half smh[];
    __half* w0   = smh;                  // part 0 W slice, [n][k] fp16
    __half* w1   = smh + TSZ;            // part 1 W slice
    __half* xbuf = smh + 2 * TSZ;        // 2 buffers, fp16

    __shared__ float s_b1[128];

    const int tid  = threadIdx.x;
    const int lane = tid & 31;

    // Load both W1 slices (W1 is [256][128] row-major; kg = row, n = col)
    for (int idx = tid; idx < 2 * 128 * 128; idx += 512) {
        int kg = idx >> 7, n = idx & 127;
        __half* wp = (kg < 128) ? w0 : w1;
        wp[n * PITCH + (kg & 127)] = __float2half(W1[idx]);
    }
    if (tid < 128) s_b1[tid] = b1[tid];
    __syncthreads();

    const bool is_consumer = tid < 256;
    const int  ptid = tid - 256;          // producers: 256 threads (8 warps)

    const float4* h4 = (const float4*)h;
    auto fill = [&](int buf, int t) {
        __half* x = xbuf + buf * TSZ;
        const int r0 = t * 128;
        #pragma unroll
        for (int i = 0; i < 16; i++) {
            int lin = ptid + 256 * i;
            int e = lin >> 5, v = lin & 31;
            int r = r0 + e;
            float4 a = make_float4(0.f, 0.f, 0.f, 0.f);
            if (r < N_NODES) a = h4[(size_t)r * 32 + v];
            __half2 p01 = __floats2half2_rn(a.x, a.y);
            __half2 p23 = __floats2half2_rn(a.z, a.w);
            int base = e * PITCH + v * 4;
            *(uint2*)&x[base] = make_uint2(*(uint32_t*)&p01, *(uint32_t*)&p23);
        }
    };

    if (!is_consumer) fill(0, blockIdx.x);
    __syncthreads();

    const int warp = tid >> 5;
    const int g    = lane >> 2;
    const int tig  = lane & 3;
    const int wm   = warp & 3;
    const int wn   = warp >> 2;           // 0/1 for consumer warps

    const uint32_t offA = ldsmA_off(lane) + (uint32_t)(wm * 32 * PITCH * 2);
    const uint32_t offB = ldsmB_off(lane) + (uint32_t)(wn * 64 * PITCH * 2);
    const uint32_t w_a[2] = { smem_u32(w0) + offB, smem_u32(w1) + offB };

    int s = 0;
    for (int t = blockIdx.x; t < NT_TILES; t += GRID, s++) {
        const int buf = s & 1;
        if (is_consumer) {
            const uint32_t x_a = smem_u32(xbuf + buf * TSZ) + offA;

            #pragma unroll
            for (int part = 0; part < 2; part++) {
                float acc[2][8][4];
                #pragma unroll
                for (int mt = 0; mt < 2; mt++)
                    #pragma unroll
                    for (int nt = 0; nt < 8; nt++)
                        #pragma unroll
                        for (int q = 0; q < 4; q++) acc[mt][nt][q] = 0.f;

                #pragma unroll
                for (int ks = 0; ks < 8; ks++) {
                    const uint32_t kb = ks * 32;

                    uint32_t a[2][4];
                    #pragma unroll
                    for (int mt = 0; mt < 2; mt++)
                        ldsm4(a[mt], x_a + mt * (16 * PITCH * 2) + kb);

                    uint32_t b_h[8][2];
                    #pragma unroll
                    for (int np = 0; np < 4; np++)
                        ldsm4(&b_h[2 * np][0], w_a[part] + np * (16 * PITCH * 2) + kb);

                    #pragma unroll
                    for (int mt = 0; mt < 2; mt++)
                        #pragma unroll
                        for (int nt = 0; nt < 8; nt++)
                            mma_f16(acc[mt][nt], a[mt], b_h[nt]);
                }

                __half* table = d_AB + (size_t)part * N_NODES * F;
                const int r_base = t * 128 + wm * 32 + g;
                #pragma unroll
                for (int mt = 0; mt < 2; mt++) {
                    #pragma unroll
                    for (int r = 0; r < 2; r++) {
                        int row = r_base + mt * 16 + r * 8;
                        if (row < N_NODES) {
                            __half* rp = table + (size_t)row * 128 + wn * 64;
                            #pragma unroll
                            for (int nt = 0; nt < 8; nt++) {
                                int c = nt * 8 + 2 * tig;
                                float bb0 = (part == 0) ? s_b1[wn * 64 + c]     : 0.f;
                                float bb1 = (part == 0) ? s_b1[wn * 64 + c + 1] : 0.f;
                                __half2 v = __floats2half2_rn(acc[mt][nt][2 * r] + bb0,
                                                              acc[mt][nt][2 * r + 1] + bb1);
                                *(__half2*)(rp + c) = v;
                            }
                        }
                    }
                }
            }
        } else {
            int tn = t + GRID;
            if (tn < NT_TILES) fill(buf ^ 1, tn);
        }
        __syncthreads();
    }
}

// ---------------------------------------------------------------------------
// Kernel 2: edge kernel — 512 threads; producer gather now uint4 (16B) loads:
// 16 lanes per edge row, 8 iterations. Consumer unchanged (single-pass fp16).
// ---------------------------------------------------------------------------
__global__ void __launch_bounds__(512, 1)
edge_kernel(const int* __restrict__ src,
            const int* __restrict__ dst,
            const float* __restrict__ W2,
            const float* __restrict__ b2,
            const float* __restrict__ W3,
            const float* __restrict__ b3,
            float* __restrict__ out) {
    extern __shared__ __half smh[];
    __half* w_h  = smh;
    __half* xbuf = smh + TSZ;

    __shared__ float s_b2[128];
    __shared__ float s_w3[256];
    __shared__ float s_b3[2];
    __shared__ float s_part[2][128][2];

    const int tid  = threadIdx.x;
    const int lane = tid & 31;

    for (int idx = tid; idx < 128 * 128; idx += 512) {
        int k = idx >> 7, n = idx & 127;
        w_h[n * PITCH + k] = __float2half(W2[idx]);
    }
    if (tid < 128) s_b2[tid] = b2[tid];
    if (tid < 256) s_w3[tid] = W3[tid];
    if (tid < 2)   s_b3[tid] = b3[tid];
    __syncthreads();

    const uint4* A4 = (const uint4*)d_AB;
    const uint4* B4 = (const uint4*)(d_AB + (size_t)N_NODES * F);
    const bool is_consumer = tid < 256;
    const int  ptid = tid - 256;

    auto fill = [&](int buf, int t) {
        __half* x = xbuf + buf * TSZ;
        const int e0 = t * 128;
        const __half2 z2 = __float2half2_rn(0.f);
        #pragma unroll
        for (int i = 0; i < 8; i++) {
            int lin = ptid + 256 * i;          // 0..2047 = 128 edges x 16
            int e = lin >> 4, v = lin & 15;    // uint4 = 8 halves per lane
            int si = src[e0 + e], di = dst[e0 + e];
            uint4 a = A4[(size_t)si * 16 + v];
            uint4 b = B4[(size_t)di * 16 + v];
            uint4 o;
            __half2 t0 = __hmax2(__hadd2(*(__half2*)&a.x, *(__half2*)&b.x), z2);
            __half2 t1 = __hmax2(__hadd2(*(__half2*)&a.y, *(__half2*)&b.y), z2);
            __half2 t2 = __hmax2(__hadd2(*(__half2*)&a.z, *(__half2*)&b.z), z2);
            __half2 t3 = __hmax2(__hadd2(*(__half2*)&a.w, *(__half2*)&b.w), z2);
            o.x = *(uint32_t*)&t0; o.y = *(uint32_t*)&t1;
            o.z = *(uint32_t*)&t2; o.w = *(uint32_t*)&t3;
            *(uint4*)&x[e * PITCH + v * 8] = o;
        }
    };

    if (!is_consumer) fill(0, blockIdx.x);
    __syncthreads();

    const int warp = tid >> 5;
    const int g    = lane >> 2;
    const int tig  = lane & 3;
    const int wm   = warp & 3;
    const int wn   = warp >> 2;

    const uint32_t offA = ldsmA_off(lane) + (uint32_t)(wm * 32 * PITCH * 2);
    const uint32_t offB = ldsmB_off(lane) + (uint32_t)(wn * 64 * PITCH * 2);
    const uint32_t wh_a = smem_u32(w_h) + offB;

    int s = 0;
    for (int t = blockIdx.x; t < TILES; t += GRID, s++) {
        const int buf = s & 1;
        if (is_consumer) {
            const uint32_t x_a = smem_u32(xbuf + buf * TSZ) + offA;

            float acc[2][8][4];
            #pragma unroll
            for (int mt = 0; mt < 2; mt++)
                #pragma unroll
                for (int nt = 0; nt < 8; nt++)
                    #pragma unroll
                    for (int q = 0; q < 4; q++) acc[mt][nt][q] = 0.f;

            #pragma unroll
            for (int ks = 0; ks < 8; ks++) {
                const uint32_t kb = ks * 32;

                uint32_t a[2][4];
                #pragma unroll
                for (int mt = 0; mt < 2; mt++)
                    ldsm4(a[mt], x_a + mt * (16 * PITCH * 2) + kb);

                uint32_t b_h[8][2];
                #pragma unroll
                for (int np = 0; np < 4; np++)
                    ldsm4(&b_h[2 * np][0], wh_a + np * (16 * PITCH * 2) + kb);

                #pragma unroll
                for (int mt = 0; mt < 2; mt++)
                    #pragma unroll
                    for (int nt = 0; nt < 8; nt++)
                        mma_f16(acc[mt][nt], a[mt], b_h[nt]);
            }

            float p[2][2][2];
            #pragma unroll
            for (int mt = 0; mt < 2; mt++)
                #pragma unroll
                for (int r = 0; r < 2; r++) { p[mt][r][0] = 0.f; p[mt][r][1] = 0.f; }

            #pragma unroll
            for (int nt = 0; nt < 8; nt++) {
                int c0 = wn * 64 + nt * 8 + 2 * tig;
                float bb0 = s_b2[c0], bb1 = s_b2[c0 + 1];
                float w300 = s_w3[c0 * 2],       w310 = s_w3[c0 * 2 + 1];
                float w301 = s_w3[(c0 + 1) * 2], w311 = s_w3[(c0 + 1) * 2 + 1];
                #pragma unroll
                for (int mt = 0; mt < 2; mt++) {
                    float x00 = fmaxf(acc[mt][nt][0] + bb0, 0.f);
                    float x01 = fmaxf(acc[mt][nt][1] + bb1, 0.f);
                    float x10 = fmaxf(acc[mt][nt][2] + bb0, 0.f);
                    float x11 = fmaxf(acc[mt][nt][3] + bb1, 0.f);
                    p[mt][0][0] = fmaf(x00, w300, fmaf(x01, w301, p[mt][0][0]));
                    p[mt][0][1] = fmaf(x00, w310, fmaf(x01, w311, p[mt][0][1]));
                    p[mt][1][0] = fmaf(x10, w300, fmaf(x11, w301, p[mt][1][0]));
                    p[mt][1][1] = fmaf(x10, w310, fmaf(x11, w311, p[mt][1][1]));
                }
            }

            #pragma unroll
            for (int mt = 0; mt < 2; mt++)
                #pragma unroll
                for (int r = 0; r < 2; r++)
                    #pragma unroll
                    for (int o = 0; o < 2; o++) {
                        float v = p[mt][r][o];
                        v += __shfl_xor_sync(0xffffffffu, v, 1);
                        v += __shfl_xor_sync(0xffffffffu, v, 2);
                        p[mt][r][o] = v;
                    }

            if (tig == 0) {
                #pragma unroll
                for (int mt = 0; mt < 2; mt++) {
                    int r0 = wm * 32 + mt * 16 + g;
                    s_part[wn][r0][0]     = p[mt][0][0];
                    s_part[wn][r0][1]     = p[mt][0][1];
                    s_part[wn][r0 + 8][0] = p[mt][1][0];
                    s_part[wn][r0 + 8][1] = p[mt][1][1];
                }
            }
            asm volatile("bar.sync 1, 256;" ::: "memory");
            out[(size_t)t * 256 + tid] =
                s_part[0][tid >> 1][tid & 1] + s_part[1][tid >> 1][tid & 1] + s_b3[tid & 1];
        } else {
            int tn = t + GRID;
            if (tn < TILES) fill(buf ^ 1, tn);
        }
        __syncthreads();
    }
}

// ---------------------------------------------------------------------------
extern "C" void kernel_launch(void* const* d_in, const int* in_sizes, int n_in,
                              void* d_out, int out_size) {
    const float* h   = (const float*)d_in[0];
    const int*   src = (const int*)d_in[1];
    const int*   dst = (const int*)d_in[2];
    const float* W1  = (const float*)d_in[3];
    const float* b1  = (const float*)d_in[4];
    const float* W2  = (const float*)d_in[5];
    const float* b2  = (const float*)d_in[6];
    const float* W3  = (const float*)d_in[7];
    const float* b3  = (const float*)d_in[8];
    float* out = (float*)d_out;

    const int node_smem = 4 * TSZ * (int)sizeof(__half);   // 139264 (w0,w1,2x xbuf)
    const int edge_smem = 3 * TSZ * (int)sizeof(__half);   // 104448
    cudaFuncSetAttribute(node_kernel, cudaFuncAttributeMaxDynamicSharedMemorySize, node_smem);
    cudaFuncSetAttribute(edge_kernel, cudaFuncAttributeMaxDynamicSharedMemorySize, edge_smem);

    node_kernel<<<GRID, 512, node_smem>>>(h, W1, b1);
    edge_kernel<<<GRID, 512, edge_smem>>>(src, dst, W2, b2, W3, b3, out);
}